// round 11
// baseline (speedup 1.0000x reference)
#include <cuda_runtime.h>
#include <string.h>
#include <math.h>

typedef unsigned long long u64;
typedef unsigned u32;

#define NQ 16
#define NL 6
#define NB 512
#define TB 12
#define TS 4096
#define NFIX 4
#define NT 16
#define TPB 512
#define EPT 8
#define TPAD 4608   // TS + TS/8 skew padding
#define NPASS (2 * NL)
#define SKEW(j) ((j) + ((j) >> 3))
#define CHUNK 128               // samples per chunk (L2 residency: 2x64MB)
#define NCHUNK (NB / CHUNK)

struct PassDesc {
    int fb[TB];          // global qubit of each local tile bit
    int fpos[NFIX];      // global qubit of each fixed bit
    int outpos[TB];      // address-bit of local bit i in NEXT pass layout
    int outfixpos[NFIX];
    int rotq[TB];        // qubit whose Rot acts on local bit lb, or -1
    u32 grow[TB];        // composed-CNOT basis images (local space)
    int nphases;         // 4 (pass A) or 2 (pass B)
    int layer;
    int synth;
    int measure;
    int rev;             // reverse CTA traversal
};

// Ping-pong state buffers: 2 x 512 x 65536 complex64 = 512 MB static scratch.
__device__ u64 g_buf0[(size_t)NB << NQ];
__device__ u64 g_buf1[(size_t)NB << NQ];
__device__ float g_part[NB * NT * NQ];

__device__ __forceinline__ u64 f2fma(u64 a, u64 b, u64 c) {
    u64 d; asm("fma.rn.f32x2 %0,%1,%2,%3;" : "=l"(d) : "l"(a), "l"(b), "l"(c)); return d;
}
__device__ __forceinline__ u64 f2mul(u64 a, u64 b) {
    u64 d; asm("mul.rn.f32x2 %0,%1,%2;" : "=l"(d) : "l"(a), "l"(b)); return d;
}
__device__ __forceinline__ u64 swap64(u64 v) {
    u32 lo, hi; asm("mov.b64 {%0,%1},%2;" : "=r"(lo), "=r"(hi) : "l"(v));
    u64 o; asm("mov.b64 %0,{%1,%2};" : "=l"(o) : "r"(hi), "r"(lo)); return o;
}
__device__ __forceinline__ u64 pack2(float lo, float hi) {
    u64 o; asm("mov.b64 %0,{%1,%2};" : "=l"(o) : "f"(lo), "f"(hi)); return o;
}

// local index of element (e, tid) in phase ph (private bits: ph0={9,10,11},
// ph1={6,7,8}, ph2={3,4,5}, ph3={0,1,2})
__device__ __forceinline__ int jmap(int ph, int e, int tid) {
    switch (ph) {
        case 0:  return (e << 9) | tid;
        case 1:  return (tid & 63) | (e << 6) | ((tid >> 6) << 9);
        case 2:  return (tid & 7) | (e << 3) | ((tid >> 3) << 6);
        default: return e | (tid << 3);
    }
}

__global__ void __launch_bounds__(TPB, 2) pass_kernel(PassDesc pd,
    const u64* __restrict__ src, u64* __restrict__ dst, int bbase,
    const float* __restrict__ x, const float* __restrict__ w)
{
    __shared__ u64 tile[TPAD];
    __shared__ u64 gmx[TB][8];
    __shared__ float sc[NQ], ss[NQ];
    __shared__ float wred[TPB / 32][NQ];

    const int tid = threadIdx.x;
    const int idx = pd.rev ? ((int)gridDim.x - 1 - (int)blockIdx.x) : (int)blockIdx.x;
    const int b = bbase + (idx >> 4);
    const int tsel = idx & 15;

    // One thread per Rot builds packed f32x2 gate constants:
    // Rot(phi,theta,omega) = RZ(omega) RY(theta) RZ(phi)
    if (tid < TB) {
        int q = pd.rotq[tid];
        if (q >= 0) {
            const float* wp = w + (pd.layer * NQ + q) * 3;
            float phi = wp[0], th = wp[1], om = wp[2];
            float stt, ct, sa, ca, sb, cb;
            sincosf(0.5f * th, &stt, &ct);
            sincosf(0.5f * (phi + om), &sa, &ca);
            sincosf(0.5f * (phi - om), &sb, &cb);
            float u00r =  ct * ca, u00i = -ct * sa;
            float u01r = -stt * cb, u01i = -stt * sb;
            float u10r =  stt * cb, u10i = -stt * sb;
            float u11r =  ct * ca, u11i =  ct * sa;
            gmx[tid][0] = pack2(u00r, u00r); gmx[tid][1] = pack2(-u00i, u00i);
            gmx[tid][2] = pack2(u01r, u01r); gmx[tid][3] = pack2(-u01i, u01i);
            gmx[tid][4] = pack2(u10r, u10r); gmx[tid][5] = pack2(-u10i, u10i);
            gmx[tid][6] = pack2(u11r, u11r); gmx[tid][7] = pack2(-u11i, u11i);
        }
    }
    if (pd.synth && tid < NQ)
        sincosf(0.5f * x[b * NQ + tid], &ss[tid], &sc[tid]);

    const u64* sg = src + ((size_t)b << NQ);
    u64* dg = dst + ((size_t)b << NQ);
    u64 v[EPT];

    if (!pd.synth) {
        // Linear read: the previous pass wrote the state in THIS pass's layout.
        const u32 rbase = (u32)tsel << TB;
#pragma unroll
        for (int e = 0; e < EPT; e++)
            v[e] = __ldcg(sg + (rbase | (e << 9) | tid));
    }
    __syncthreads();
    if (pd.synth) {
        // amp(g) = (-i)^popc(g) * prod_q (bit_q ? sin(x_q/2) : cos(x_q/2))
        u32 gbase = 0;
#pragma unroll
        for (int i = 0; i < NFIX; i++)
            gbase |= ((u32)(tsel >> i) & 1u) << pd.fpos[i];
#pragma unroll
        for (int lb = 0; lb < 9; lb++)
            gbase |= ((u32)(tid >> lb) & 1u) << pd.fb[lb];
        const u32 f9 = 1u << pd.fb[9], f10 = 1u << pd.fb[10], f11 = 1u << pd.fb[11];
#pragma unroll
        for (int e = 0; e < EPT; e++) {
            u32 g = gbase | ((e & 1) ? f9 : 0u) | ((e & 2) ? f10 : 0u) | ((e & 4) ? f11 : 0u);
            float mag = 1.0f;
#pragma unroll
            for (int q = 0; q < NQ; q++)
                mag *= ((g >> q) & 1u) ? ss[q] : sc[q];
            int k = __popc(g) & 3;
            float re = (k == 0) ? mag : ((k == 2) ? -mag : 0.0f);
            float im = (k == 1) ? -mag : ((k == 3) ? mag : 0.0f);
            v[e] = pack2(re, im);
        }
    }

    const int nph = pd.nphases;
    for (int ph = 0; ph < nph; ph++) {
        if (ph > 0) {
#pragma unroll
            for (int e = 0; e < EPT; e++) {
                int j = jmap(ph, e, tid);
                v[e] = tile[SKEW(j)];
            }
        }
        const int lb0 = 9 - 3 * ph;
#pragma unroll
        for (int s = 0; s < 3; s++) {
            int lb = lb0 + s;
            if (pd.rotq[lb] >= 0) {
                u64 c00r = gmx[lb][0], c00i = gmx[lb][1], c01r = gmx[lb][2], c01i = gmx[lb][3];
                u64 c10r = gmx[lb][4], c10i = gmx[lb][5], c11r = gmx[lb][6], c11i = gmx[lb][7];
#pragma unroll
                for (int p = 0; p < 4; p++) {
                    int elo = ((p >> s) << (s + 1)) | (p & ((1 << s) - 1));
                    int ehi = elo | (1 << s);
                    u64 a = v[elo], bb = v[ehi];
                    u64 sa_ = swap64(a), sb_ = swap64(bb);
                    v[elo] = f2fma(c00r, a, f2fma(c00i, sa_, f2fma(c01r, bb, f2mul(c01i, sb_))));
                    v[ehi] = f2fma(c10r, a, f2fma(c10i, sa_, f2fma(c11r, bb, f2mul(c11i, sb_))));
                }
            }
        }
        if (ph > 0) __syncthreads();   // all tile reads done before overwrite
#pragma unroll
        for (int e = 0; e < EPT; e++) {
            int j = jmap(ph, e, tid);
            tile[SKEW(j)] = v[e];
        }
        __syncthreads();
    }

    // gather: f[j] = s[G(j)], G = composed CNOT chain (XOR-linear, local space)
    u32 srcbase = 0;
#pragma unroll
    for (int lb = 0; lb < 9; lb++)
        if ((tid >> lb) & 1) srcbase ^= pd.grow[lb];
    const u32 g9 = pd.grow[9], g10 = pd.grow[10], g11 = pd.grow[11];

    if (!pd.measure) {
        // write into NEXT pass's layout in the OTHER buffer (race-free ping-pong)
        u32 wbase = 0;
#pragma unroll
        for (int i = 0; i < NFIX; i++)
            wbase |= ((u32)(tsel >> i) & 1u) << pd.outfixpos[i];
#pragma unroll
        for (int lb = 0; lb < 9; lb++)
            wbase |= ((u32)(tid >> lb) & 1u) << pd.outpos[lb];
        const u32 w9 = 1u << pd.outpos[9], w10 = 1u << pd.outpos[10], w11 = 1u << pd.outpos[11];
#pragma unroll
        for (int e = 0; e < EPT; e++) {
            u32 s2 = srcbase ^ ((e & 1) ? g9 : 0u) ^ ((e & 2) ? g10 : 0u) ^ ((e & 4) ? g11 : 0u);
            u32 wa = wbase | ((e & 1) ? w9 : 0u) | ((e & 2) ? w10 : 0u) | ((e & 4) ? w11 : 0u);
            dg[wa] = tile[SKEW(s2)];
        }
    } else {
        u32 gbase = 0;
#pragma unroll
        for (int i = 0; i < NFIX; i++)
            gbase |= ((u32)(tsel >> i) & 1u) << pd.fpos[i];
#pragma unroll
        for (int lb = 0; lb < 9; lb++)
            gbase |= ((u32)(tid >> lb) & 1u) << pd.fb[lb];
        float p8[EPT];
#pragma unroll
        for (int e = 0; e < EPT; e++) {
            u32 s2 = srcbase ^ ((e & 1) ? g9 : 0u) ^ ((e & 2) ? g10 : 0u) ^ ((e & 4) ? g11 : 0u);
            u64 val = tile[SKEW(s2)];
            float2 c = *(float2*)&val;
            p8[e] = c.x * c.x + c.y * c.y;
        }
        float a0 = p8[0] + p8[1], a1 = p8[2] + p8[3], a2 = p8[4] + p8[5], a3 = p8[6] + p8[7];
        float b0 = a0 + a1, b1 = a2 + a3;
        float s_ = b0 + b1;
        float z0 = (p8[0] - p8[1]) + (p8[2] - p8[3]) + (p8[4] - p8[5]) + (p8[6] - p8[7]);
        float z1 = (a0 - a1) + (a2 - a3);
        float z2 = b0 - b1;
        float acc[NQ];
#pragma unroll
        for (int q = 0; q < NQ; q++) {
            float t = ((gbase >> q) & 1u) ? -s_ : s_;
            if (q == pd.fb[9])  t = z0;   // gbase bit is 0 there; z already signed
            if (q == pd.fb[10]) t = z1;
            if (q == pd.fb[11]) t = z2;
            acc[q] = t;
        }
#pragma unroll
        for (int q = 0; q < NQ; q++)
#pragma unroll
            for (int o = 16; o > 0; o >>= 1)
                acc[q] += __shfl_xor_sync(0xffffffffu, acc[q], o);
        if ((tid & 31) == 0) {
#pragma unroll
            for (int q = 0; q < NQ; q++)
                wred[tid >> 5][q] = acc[q];
        }
        __syncthreads();
        if (tid < NQ) {
            float sm = 0.0f;
#pragma unroll
            for (int wg = 0; wg < TPB / 32; wg++)
                sm += wred[wg][tid];
            g_part[((b << 4) | tsel) * NQ + tid] = sm;
        }
    }
}

__global__ void finalize_kernel(float* __restrict__ out)
{
    int i = blockIdx.x * blockDim.x + threadIdx.x;
    if (i < NB * NQ) {
        int b = i / NQ, q = i % NQ;
        float s = 0.0f;
#pragma unroll
        for (int t = 0; t < NT; t++)
            s += g_part[(b * NT + t) * NQ + q];
        out[i] = s;
    }
}

// ---------------------------------------------------------------------------
// Host scheduling: exact gate schedule proven in R4/R6/R8 (pass A = Rot 0..11
// + in-tile ring CNOTs; pass B = Rot 12..15 + deferred CNOTs; deferral
// commutes for all r<=6). State between passes is stored bit-permuted (next
// pass's free bits at addr bits 0..11) in PING-PONG buffers; execution is
// CHUNKED over samples so each pass boundary stays L2-resident.
// ---------------------------------------------------------------------------
static void compose_cnots(u32* grow, const u32* cm, const u32* tm, int ncn)
{
    for (int lb = 0; lb < TB; lb++) {
        u32 s = 1u << lb;
        for (int i = ncn - 1; i >= 0; i--)
            if (s & cm[i]) s ^= tm[i];
        grow[lb] = s;
    }
}

static void order_tile(const bool* inSet, const int* prevLanes,
                       const bool* prefSet, const bool* rotSet, int* fb)
{
    bool used[NQ] = {};
    int n = 0;
    if (prevLanes) {
        for (int i = 0; i < 5; i++) {
            int q = prevLanes[i];
            if (q >= 0 && inSet[q] && !used[q] && !rotSet[q]) { fb[n++] = q; used[q] = true; }
        }
    }
    while (n < 5) {
        int pick = -1;
        for (int tier = 0; tier < 4 && pick < 0; tier++)
            for (int q = 0; q < NQ && pick < 0; q++)
                if (inSet[q] && !used[q]) {
                    bool ok;
                    switch (tier) {
                        case 0: ok = prefSet && prefSet[q] && !rotSet[q]; break;
                        case 1: ok = !rotSet[q]; break;
                        case 2: ok = prefSet && prefSet[q]; break;
                        default: ok = true; break;
                    }
                    if (ok) pick = q;
                }
        fb[n++] = pick; used[pick] = true;
    }
    for (int q = 0; q < NQ; q++)            // middle: remaining non-rot
        if (inSet[q] && !used[q] && !rotSet[q]) { fb[n++] = q; used[q] = true; }
    for (int q = 0; q < NQ; q++)            // rot qubits last (high local bits)
        if (inSet[q] && !used[q]) { fb[n++] = q; used[q] = true; }
}

static void build_passes(PassDesc* pds)
{
    static bool tiles[NPASS][NQ], rots[NPASS][NQ];
    static int cms[NPASS][NQ], tms[NPASS][NQ], ncns[NPASS];
    static int fbs[NPASS][TB], fposs[NPASS][NFIX];

    for (int l = 0; l < NL; l++) {
        int r = (l % (NQ - 1)) + 1;
        bool inA[NQ];
        for (int q = 0; q < NQ; q++)
            inA[q] = (q <= 11 && (q + r) % NQ <= 11);

        int mA = 2 * l, mB = 2 * l + 1;
        for (int q = 0; q < NQ; q++) {
            tiles[mA][q] = (q < TB);
            rots[mA][q] = (q < TB);
        }
        ncns[mA] = 0;
        for (int q = 0; q < NQ; q++)
            if (inA[q]) { cms[mA][ncns[mA]] = q; tms[mA][ncns[mA]] = (q + r) % NQ; ncns[mA]++; }

        bool touched[NQ] = {};
        for (int q = TB; q < NQ; q++) touched[q] = true;
        for (int q = 0; q < NQ; q++)
            if (!inA[q]) { touched[q] = true; touched[(q + r) % NQ] = true; }
        int cnt = 0;
        for (int q = 0; q < NQ; q++) if (touched[q]) cnt++;
        for (int q = 0; q < NQ && cnt < TB; q++)
            if (!touched[q]) { touched[q] = true; cnt++; }
        for (int q = 0; q < NQ; q++) {
            tiles[mB][q] = touched[q];
            rots[mB][q] = (q >= TB);
        }
        ncns[mB] = 0;
        for (int q = 0; q < NQ; q++)
            if (!inA[q]) { cms[mB][ncns[mB]] = q; tms[mB][ncns[mB]] = (q + r) % NQ; ncns[mB]++; }
    }

    int prevLanes[5] = {-1, -1, -1, -1, -1};
    for (int m = 0; m < NPASS; m++) {
        bool pref[NQ]; bool hasPref = false;
        for (int q = 0; q < NQ; q++) pref[q] = false;
        if (m + 1 < NPASS) {
            for (int q = 0; q < NQ; q++) {
                bool p = tiles[m + 1][q];
                if (m + 2 < NPASS) p = p && tiles[m + 2][q];
                pref[q] = p;
            }
            hasPref = true;
        }
        order_tile(tiles[m], (m > 0) ? prevLanes : (const int*)0,
                   hasPref ? pref : (const bool*)0, rots[m], fbs[m]);
        for (int i = 0; i < 5; i++) prevLanes[i] = fbs[m][i];
        int xi = 0;
        for (int q = 0; q < NQ; q++)
            if (!tiles[m][q]) fposs[m][xi++] = q;
    }

    for (int m = 0; m < NPASS; m++) {
        PassDesc& pd = pds[m];
        memset(&pd, 0, sizeof(pd));
        pd.layer = m / 2;
        pd.synth = (m == 0);
        pd.measure = (m == NPASS - 1);
        pd.rev = (m & 1);
        int lq[NQ];
        for (int q = 0; q < NQ; q++) lq[q] = -1;
        for (int i = 0; i < TB; i++) { pd.fb[i] = fbs[m][i]; lq[fbs[m][i]] = i; }
        for (int i = 0; i < NFIX; i++) pd.fpos[i] = fposs[m][i];
        int minRot = TB;
        for (int i = 0; i < TB; i++) {
            pd.rotq[i] = rots[m][pd.fb[i]] ? pd.fb[i] : -1;
            if (pd.rotq[i] >= 0 && i < minRot) minRot = i;
        }
        pd.nphases = (TB - minRot + 2) / 3;   // A: 4, B: 2
        u32 cm[NQ], tm[NQ];
        for (int i = 0; i < ncns[m]; i++) {
            cm[i] = 1u << lq[cms[m][i]];
            tm[i] = 1u << lq[tms[m][i]];
        }
        compose_cnots(pd.grow, cm, tm, ncns[m]);
        if (m + 1 < NPASS) {
            int pos[NQ];
            for (int i = 0; i < TB; i++)   pos[fbs[m + 1][i]] = i;
            for (int i = 0; i < NFIX; i++) pos[fposs[m + 1][i]] = TB + i;
            for (int i = 0; i < TB; i++)   pd.outpos[i] = pos[pd.fb[i]];
            for (int i = 0; i < NFIX; i++) pd.outfixpos[i] = pos[pd.fpos[i]];
        }
    }
}

extern "C" void kernel_launch(void* const* d_in, const int* in_sizes, int n_in,
                              void* d_out, int out_size)
{
    const float* x = (const float*)d_in[0];   // (512, 16)
    const float* w = (const float*)d_in[1];   // (6, 16, 3)
    float* out = (float*)d_out;               // (512, 16) float32

    PassDesc pds[NPASS];
    build_passes(pds);

    u64* bufs[2];
    cudaGetSymbolAddress((void**)&bufs[0], g_buf0);
    cudaGetSymbolAddress((void**)&bufs[1], g_buf1);

    dim3 grid(CHUNK * NT);
    for (int c = 0; c < NCHUNK; c++) {
        int bbase = c * CHUNK;
        for (int p = 0; p < NPASS; p++) {
            const u64* src = bufs[p & 1];
            u64* dst = bufs[(p + 1) & 1];
            pass_kernel<<<grid, TPB>>>(pds[p], src, dst, bbase, x, w);
        }
    }

    finalize_kernel<<<(NB * NQ + 255) / 256, 256>>>(out);
}

// round 13
// speedup vs baseline: 1.1408x; 1.1408x over previous
#include <cuda_runtime.h>
#include <string.h>
#include <math.h>

typedef unsigned long long u64;
typedef unsigned u32;

#define NQ 16
#define NL 6
#define NB 512
#define TB 12
#define TS 4096
#define NFIX 4
#define NT 16
#define TPB 512
#define EPT 8
#define TPAD 4608   // TS + TS/8 skew padding
#define NPASS (2 * NL)
#define SKEW(j) ((j) + ((j) >> 3))

struct PassDesc {
    int fb[TB];          // global qubit of each local tile bit
    int fpos[NFIX];      // global qubit of each fixed bit
    int outpos[TB];      // address-bit of local bit i in NEXT pass layout
    int outfixpos[NFIX];
    int rotq[TB];        // qubit whose Rot acts on local bit lb, or -1
    u32 grow[TB];        // composed-CNOT basis images (local space)
    int nphases;         // 4 (pass A) or 2 (pass B)
    int layer;
    int synth;
    int measure;
    int rev;             // reverse CTA traversal (L2 producer->consumer locality)
};

// Ping-pong state buffers: 2 x 512 x 65536 complex64 = 512 MB static scratch.
__device__ u64 g_buf0[(size_t)NB << NQ];
__device__ u64 g_buf1[(size_t)NB << NQ];
__device__ float g_part[NB * NT * NQ];

__device__ __forceinline__ u64 f2fma(u64 a, u64 b, u64 c) {
    u64 d; asm("fma.rn.f32x2 %0,%1,%2,%3;" : "=l"(d) : "l"(a), "l"(b), "l"(c)); return d;
}
__device__ __forceinline__ u64 f2mul(u64 a, u64 b) {
    u64 d; asm("mul.rn.f32x2 %0,%1,%2;" : "=l"(d) : "l"(a), "l"(b)); return d;
}
__device__ __forceinline__ u64 swap64(u64 v) {
    u32 lo, hi; asm("mov.b64 {%0,%1},%2;" : "=r"(lo), "=r"(hi) : "l"(v));
    u64 o; asm("mov.b64 %0,{%1,%2};" : "=l"(o) : "r"(hi), "r"(lo)); return o;
}
__device__ __forceinline__ u64 pack2(float lo, float hi) {
    u64 o; asm("mov.b64 %0,{%1,%2};" : "=l"(o) : "f"(lo), "f"(hi)); return o;
}

// local index of element (e, tid) in phase ph (private bits: ph0={9,10,11},
// ph1={6,7,8}, ph2={3,4,5}, ph3={0,1,2})
__device__ __forceinline__ int jmap(int ph, int e, int tid) {
    switch (ph) {
        case 0:  return (e << 9) | tid;
        case 1:  return (tid & 63) | (e << 6) | ((tid >> 6) << 9);
        case 2:  return (tid & 7) | (e << 3) | ((tid >> 3) << 6);
        default: return e | (tid << 3);
    }
}

__global__ void __launch_bounds__(TPB, 2) pass_kernel(PassDesc pd,
    const u64* __restrict__ src, u64* __restrict__ dst,
    const float* __restrict__ x, const float* __restrict__ w)
{
    __shared__ u64 tile[TPAD];
    __shared__ u64 gmx[TB][8];
    __shared__ float sc[NQ], ss[NQ];
    __shared__ float wred[TPB / 32][NQ];

    const int tid = threadIdx.x;
    const int idx = pd.rev ? ((int)gridDim.x - 1 - (int)blockIdx.x) : (int)blockIdx.x;
    const int b = idx >> 4;
    const int tsel = idx & 15;

    // One thread per Rot builds packed f32x2 gate constants:
    // Rot(phi,theta,omega) = RZ(omega) RY(theta) RZ(phi)
    if (tid < TB) {
        int q = pd.rotq[tid];
        if (q >= 0) {
            const float* wp = w + (pd.layer * NQ + q) * 3;
            float phi = wp[0], th = wp[1], om = wp[2];
            float stt, ct, sa, ca, sb, cb;
            sincosf(0.5f * th, &stt, &ct);
            sincosf(0.5f * (phi + om), &sa, &ca);
            sincosf(0.5f * (phi - om), &sb, &cb);
            float u00r =  ct * ca, u00i = -ct * sa;
            float u01r = -stt * cb, u01i = -stt * sb;
            float u10r =  stt * cb, u10i = -stt * sb;
            float u11r =  ct * ca, u11i =  ct * sa;
            gmx[tid][0] = pack2(u00r, u00r); gmx[tid][1] = pack2(-u00i, u00i);
            gmx[tid][2] = pack2(u01r, u01r); gmx[tid][3] = pack2(-u01i, u01i);
            gmx[tid][4] = pack2(u10r, u10r); gmx[tid][5] = pack2(-u10i, u10i);
            gmx[tid][6] = pack2(u11r, u11r); gmx[tid][7] = pack2(-u11i, u11i);
        }
    }
    if (pd.synth && tid < NQ)
        sincosf(0.5f * x[b * NQ + tid], &ss[tid], &sc[tid]);

    const u64* sg = src + ((size_t)b << NQ);
    u64* dg = dst + ((size_t)b << NQ);
    u64 v[EPT];

    if (!pd.synth) {
        // Linear read: the previous pass wrote the state in THIS pass's layout.
        const u32 rbase = (u32)tsel << TB;
#pragma unroll
        for (int e = 0; e < EPT; e++)
            v[e] = __ldcg(sg + (rbase | (e << 9) | tid));
    }
    __syncthreads();
    if (pd.synth) {
        // amp(g) = (-i)^popc(g) * prod_q (bit_q ? sin(x_q/2) : cos(x_q/2))
        u32 gbase = 0;
#pragma unroll
        for (int i = 0; i < NFIX; i++)
            gbase |= ((u32)(tsel >> i) & 1u) << pd.fpos[i];
#pragma unroll
        for (int lb = 0; lb < 9; lb++)
            gbase |= ((u32)(tid >> lb) & 1u) << pd.fb[lb];
        const u32 f9 = 1u << pd.fb[9], f10 = 1u << pd.fb[10], f11 = 1u << pd.fb[11];
#pragma unroll
        for (int e = 0; e < EPT; e++) {
            u32 g = gbase | ((e & 1) ? f9 : 0u) | ((e & 2) ? f10 : 0u) | ((e & 4) ? f11 : 0u);
            float mag = 1.0f;
#pragma unroll
            for (int q = 0; q < NQ; q++)
                mag *= ((g >> q) & 1u) ? ss[q] : sc[q];
            int k = __popc(g) & 3;
            float re = (k == 0) ? mag : ((k == 2) ? -mag : 0.0f);
            float im = (k == 1) ? -mag : ((k == 3) ? mag : 0.0f);
            v[e] = pack2(re, im);
        }
    }

    const int nph = pd.nphases;
    for (int ph = 0; ph < nph; ph++) {
        if (ph > 0) {
#pragma unroll
            for (int e = 0; e < EPT; e++) {
                int j = jmap(ph, e, tid);
                v[e] = tile[SKEW(j)];
            }
        }
        const int lb0 = 9 - 3 * ph;
#pragma unroll
        for (int s = 0; s < 3; s++) {
            int lb = lb0 + s;
            if (pd.rotq[lb] >= 0) {
                u64 c00r = gmx[lb][0], c00i = gmx[lb][1], c01r = gmx[lb][2], c01i = gmx[lb][3];
                u64 c10r = gmx[lb][4], c10i = gmx[lb][5], c11r = gmx[lb][6], c11i = gmx[lb][7];
#pragma unroll
                for (int p = 0; p < 4; p++) {
                    int elo = ((p >> s) << (s + 1)) | (p & ((1 << s) - 1));
                    int ehi = elo | (1 << s);
                    u64 a = v[elo], bb = v[ehi];
                    u64 sa_ = swap64(a), sb_ = swap64(bb);
                    v[elo] = f2fma(c00r, a, f2fma(c00i, sa_, f2fma(c01r, bb, f2mul(c01i, sb_))));
                    v[ehi] = f2fma(c10r, a, f2fma(c10i, sa_, f2fma(c11r, bb, f2mul(c11i, sb_))));
                }
            }
        }
        if (ph > 0) __syncthreads();   // all tile reads done before overwrite
#pragma unroll
        for (int e = 0; e < EPT; e++) {
            int j = jmap(ph, e, tid);
            tile[SKEW(j)] = v[e];
        }
        __syncthreads();
    }

    // gather: f[j] = s[G(j)], G = composed CNOT chain (XOR-linear, local space)
    u32 srcbase = 0;
#pragma unroll
    for (int lb = 0; lb < 9; lb++)
        if ((tid >> lb) & 1) srcbase ^= pd.grow[lb];
    const u32 g9 = pd.grow[9], g10 = pd.grow[10], g11 = pd.grow[11];

    if (!pd.measure) {
        // write into NEXT pass's layout in the OTHER buffer (race-free ping-pong)
        u32 wbase = 0;
#pragma unroll
        for (int i = 0; i < NFIX; i++)
            wbase |= ((u32)(tsel >> i) & 1u) << pd.outfixpos[i];
#pragma unroll
        for (int lb = 0; lb < 9; lb++)
            wbase |= ((u32)(tid >> lb) & 1u) << pd.outpos[lb];
        const u32 w9 = 1u << pd.outpos[9], w10 = 1u << pd.outpos[10], w11 = 1u << pd.outpos[11];
#pragma unroll
        for (int e = 0; e < EPT; e++) {
            u32 s2 = srcbase ^ ((e & 1) ? g9 : 0u) ^ ((e & 2) ? g10 : 0u) ^ ((e & 4) ? g11 : 0u);
            u32 wa = wbase | ((e & 1) ? w9 : 0u) | ((e & 2) ? w10 : 0u) | ((e & 4) ? w11 : 0u);
            dg[wa] = tile[SKEW(s2)];
        }
    } else {
        u32 gbase = 0;
#pragma unroll
        for (int i = 0; i < NFIX; i++)
            gbase |= ((u32)(tsel >> i) & 1u) << pd.fpos[i];
#pragma unroll
        for (int lb = 0; lb < 9; lb++)
            gbase |= ((u32)(tid >> lb) & 1u) << pd.fb[lb];
        float p8[EPT];
#pragma unroll
        for (int e = 0; e < EPT; e++) {
            u32 s2 = srcbase ^ ((e & 1) ? g9 : 0u) ^ ((e & 2) ? g10 : 0u) ^ ((e & 4) ? g11 : 0u);
            u64 val = tile[SKEW(s2)];
            float2 c = *(float2*)&val;
            p8[e] = c.x * c.x + c.y * c.y;
        }
        float a0 = p8[0] + p8[1], a1 = p8[2] + p8[3], a2 = p8[4] + p8[5], a3 = p8[6] + p8[7];
        float b0 = a0 + a1, b1 = a2 + a3;
        float s_ = b0 + b1;
        float z0 = (p8[0] - p8[1]) + (p8[2] - p8[3]) + (p8[4] - p8[5]) + (p8[6] - p8[7]);
        float z1 = (a0 - a1) + (a2 - a3);
        float z2 = b0 - b1;
        float acc[NQ];
#pragma unroll
        for (int q = 0; q < NQ; q++) {
            float t = ((gbase >> q) & 1u) ? -s_ : s_;
            if (q == pd.fb[9])  t = z0;   // gbase bit is 0 there; z already signed
            if (q == pd.fb[10]) t = z1;
            if (q == pd.fb[11]) t = z2;
            acc[q] = t;
        }
#pragma unroll
        for (int q = 0; q < NQ; q++)
#pragma unroll
            for (int o = 16; o > 0; o >>= 1)
                acc[q] += __shfl_xor_sync(0xffffffffu, acc[q], o);
        if ((tid & 31) == 0) {
#pragma unroll
            for (int q = 0; q < NQ; q++)
                wred[tid >> 5][q] = acc[q];
        }
        __syncthreads();
        if (tid < NQ) {
            float sm = 0.0f;
#pragma unroll
            for (int wg = 0; wg < TPB / 32; wg++)
                sm += wred[wg][tid];
            g_part[((b << 4) | tsel) * NQ + tid] = sm;
        }
    }
}

__global__ void finalize_kernel(float* __restrict__ out)
{
    int i = blockIdx.x * blockDim.x + threadIdx.x;
    if (i < NB * NQ) {
        int b = i / NQ, q = i % NQ;
        float s = 0.0f;
#pragma unroll
        for (int t = 0; t < NT; t++)
            s += g_part[(b * NT + t) * NQ + q];
        out[i] = s;
    }
}

// ---------------------------------------------------------------------------
// Host scheduling: exact gate schedule proven in R4/R6/R8 (pass A = Rot 0..11
// + in-tile ring CNOTs; pass B = Rot 12..15 + deferred CNOTs; deferral
// commutes for all r<=6). State between passes is stored bit-permuted (next
// pass's free bits at addr bits 0..11) in PING-PONG buffers. Full-batch grid
// (chunking regressed in R11). NEW this round: lane inheritance no longer
// rejects rot qubits, so every pass boundary keeps the writer's lane qubits in
// the reader's low local bits -> coalesced stores on ALL boundaries. This is
// free: inherited lanes are always <=11 so pass-B rots (12..15) stay in the
// top 4 local bits (nphases=2); pass A has minRot=0 either way (nphases=4).
// ---------------------------------------------------------------------------
static void compose_cnots(u32* grow, const u32* cm, const u32* tm, int ncn)
{
    for (int lb = 0; lb < TB; lb++) {
        u32 s = 1u << lb;
        for (int i = ncn - 1; i >= 0; i--)
            if (s & cm[i]) s ^= tm[i];
        grow[lb] = s;
    }
}

static void order_tile(const bool* inSet, const int* prevLanes,
                       const bool* prefSet, const bool* rotSet, int* fb)
{
    bool used[NQ] = {};
    int n = 0;
    if (prevLanes) {
        for (int i = 0; i < 5; i++) {
            int q = prevLanes[i];
            // Inherit regardless of rot status (see header comment).
            if (q >= 0 && inSet[q] && !used[q]) { fb[n++] = q; used[q] = true; }
        }
    }
    while (n < 5) {
        int pick = -1;
        for (int tier = 0; tier < 4 && pick < 0; tier++)
            for (int q = 0; q < NQ && pick < 0; q++)
                if (inSet[q] && !used[q]) {
                    bool ok;
                    switch (tier) {
                        case 0: ok = prefSet && prefSet[q] && !rotSet[q]; break;
                        case 1: ok = !rotSet[q]; break;
                        case 2: ok = prefSet && prefSet[q]; break;
                        default: ok = true; break;
                    }
                    if (ok) pick = q;
                }
        fb[n++] = pick; used[pick] = true;
    }
    for (int q = 0; q < NQ; q++)            // middle: remaining non-rot
        if (inSet[q] && !used[q] && !rotSet[q]) { fb[n++] = q; used[q] = true; }
    for (int q = 0; q < NQ; q++)            // rot qubits last (high local bits)
        if (inSet[q] && !used[q]) { fb[n++] = q; used[q] = true; }
}

static void build_passes(PassDesc* pds)
{
    static bool tiles[NPASS][NQ], rots[NPASS][NQ];
    static int cms[NPASS][NQ], tms[NPASS][NQ], ncns[NPASS];
    static int fbs[NPASS][TB], fposs[NPASS][NFIX];

    for (int l = 0; l < NL; l++) {
        int r = (l % (NQ - 1)) + 1;
        bool inA[NQ];
        for (int q = 0; q < NQ; q++)
            inA[q] = (q <= 11 && (q + r) % NQ <= 11);

        int mA = 2 * l, mB = 2 * l + 1;
        for (int q = 0; q < NQ; q++) {
            tiles[mA][q] = (q < TB);
            rots[mA][q] = (q < TB);
        }
        ncns[mA] = 0;
        for (int q = 0; q < NQ; q++)
            if (inA[q]) { cms[mA][ncns[mA]] = q; tms[mA][ncns[mA]] = (q + r) % NQ; ncns[mA]++; }

        bool touched[NQ] = {};
        for (int q = TB; q < NQ; q++) touched[q] = true;
        for (int q = 0; q < NQ; q++)
            if (!inA[q]) { touched[q] = true; touched[(q + r) % NQ] = true; }
        int cnt = 0;
        for (int q = 0; q < NQ; q++) if (touched[q]) cnt++;
        for (int q = 0; q < NQ && cnt < TB; q++)
            if (!touched[q]) { touched[q] = true; cnt++; }
        for (int q = 0; q < NQ; q++) {
            tiles[mB][q] = touched[q];
            rots[mB][q] = (q >= TB);
        }
        ncns[mB] = 0;
        for (int q = 0; q < NQ; q++)
            if (!inA[q]) { cms[mB][ncns[mB]] = q; tms[mB][ncns[mB]] = (q + r) % NQ; ncns[mB]++; }
    }

    int prevLanes[5] = {-1, -1, -1, -1, -1};
    for (int m = 0; m < NPASS; m++) {
        bool pref[NQ]; bool hasPref = false;
        for (int q = 0; q < NQ; q++) pref[q] = false;
        if (m + 1 < NPASS) {
            for (int q = 0; q < NQ; q++) {
                bool p = tiles[m + 1][q];
                if (m + 2 < NPASS) p = p && tiles[m + 2][q];
                pref[q] = p;
            }
            hasPref = true;
        }
        order_tile(tiles[m], (m > 0) ? prevLanes : (const int*)0,
                   hasPref ? pref : (const bool*)0, rots[m], fbs[m]);
        for (int i = 0; i < 5; i++) prevLanes[i] = fbs[m][i];
        int xi = 0;
        for (int q = 0; q < NQ; q++)
            if (!tiles[m][q]) fposs[m][xi++] = q;
    }

    for (int m = 0; m < NPASS; m++) {
        PassDesc& pd = pds[m];
        memset(&pd, 0, sizeof(pd));
        pd.layer = m / 2;
        pd.synth = (m == 0);
        pd.measure = (m == NPASS - 1);
        pd.rev = (m & 1);
        int lq[NQ];
        for (int q = 0; q < NQ; q++) lq[q] = -1;
        for (int i = 0; i < TB; i++) { pd.fb[i] = fbs[m][i]; lq[fbs[m][i]] = i; }
        for (int i = 0; i < NFIX; i++) pd.fpos[i] = fposs[m][i];
        int minRot = TB;
        for (int i = 0; i < TB; i++) {
            pd.rotq[i] = rots[m][pd.fb[i]] ? pd.fb[i] : -1;
            if (pd.rotq[i] >= 0 && i < minRot) minRot = i;
        }
        pd.nphases = (TB - minRot + 2) / 3;   // A: 4, B: 2
        u32 cm[NQ], tm[NQ];
        for (int i = 0; i < ncns[m]; i++) {
            cm[i] = 1u << lq[cms[m][i]];
            tm[i] = 1u << lq[tms[m][i]];
        }
        compose_cnots(pd.grow, cm, tm, ncns[m]);
        if (m + 1 < NPASS) {
            int pos[NQ];
            for (int i = 0; i < TB; i++)   pos[fbs[m + 1][i]] = i;
            for (int i = 0; i < NFIX; i++) pos[fposs[m + 1][i]] = TB + i;
            for (int i = 0; i < TB; i++)   pd.outpos[i] = pos[pd.fb[i]];
            for (int i = 0; i < NFIX; i++) pd.outfixpos[i] = pos[pd.fpos[i]];
        }
    }
}

extern "C" void kernel_launch(void* const* d_in, const int* in_sizes, int n_in,
                              void* d_out, int out_size)
{
    const float* x = (const float*)d_in[0];   // (512, 16)
    const float* w = (const float*)d_in[1];   // (6, 16, 3)
    float* out = (float*)d_out;               // (512, 16) float32

    PassDesc pds[NPASS];
    build_passes(pds);

    u64* bufs[2];
    cudaGetSymbolAddress((void**)&bufs[0], g_buf0);
    cudaGetSymbolAddress((void**)&bufs[1], g_buf1);

    dim3 grid(NB * NT);
    for (int p = 0; p < NPASS; p++) {
        const u64* src = bufs[p & 1];
        u64* dst = bufs[(p + 1) & 1];
        pass_kernel<<<grid, TPB>>>(pds[p], src, dst, x, w);
    }

    finalize_kernel<<<(NB * NQ + 255) / 256, 256>>>(out);
}

// round 15
// speedup vs baseline: 1.3862x; 1.2151x over previous
#include <cuda_runtime.h>
#include <string.h>
#include <math.h>

typedef unsigned long long u64;
typedef unsigned u32;

#define NQ 16
#define NL 6
#define NB 512
#define TB 12
#define TS 4096
#define NFIX 4
#define NT 16
#define TPB 256
#define EPT 16
#define TPAD 4352   // TS + TS/16 skew padding
#define NPASS (2 * NL)
#define SKEW(j) ((j) + ((j) >> 4))

struct PassDesc {
    int fb[TB];          // global qubit of each local tile bit
    int fpos[NFIX];      // global qubit of each fixed bit
    int outpos[TB];      // address-bit of local bit i in NEXT pass layout
    int outfixpos[NFIX];
    int rotq[TB];        // qubit whose Rot acts on local bit lb, or -1
    u32 grow[TB];        // composed-CNOT basis images (local space)
    int nphases;         // 3 (pass A) or 1 (pass B)
    int layer;
    int synth;
    int measure;
    int rev;             // reverse CTA traversal (L2 producer->consumer locality)
};

// Ping-pong state buffers: 2 x 512 x 65536 complex64 = 512 MB static scratch.
__device__ u64 g_buf0[(size_t)NB << NQ];
__device__ u64 g_buf1[(size_t)NB << NQ];
__device__ float g_part[NB * NT * NQ];

__device__ __forceinline__ u64 f2fma(u64 a, u64 b, u64 c) {
    u64 d; asm("fma.rn.f32x2 %0,%1,%2,%3;" : "=l"(d) : "l"(a), "l"(b), "l"(c)); return d;
}
__device__ __forceinline__ u64 f2mul(u64 a, u64 b) {
    u64 d; asm("mul.rn.f32x2 %0,%1,%2;" : "=l"(d) : "l"(a), "l"(b)); return d;
}
__device__ __forceinline__ u64 swap64(u64 v) {
    u32 lo, hi; asm("mov.b64 {%0,%1},%2;" : "=r"(lo), "=r"(hi) : "l"(v));
    u64 o; asm("mov.b64 %0,{%1,%2};" : "=l"(o) : "r"(hi), "r"(lo)); return o;
}
__device__ __forceinline__ u64 pack2(float lo, float hi) {
    u64 o; asm("mov.b64 %0,{%1,%2};" : "=l"(o) : "f"(lo), "f"(hi)); return o;
}

// local index of element (e, tid) in phase ph
// private bits: ph0={8..11}, ph1={4..7}, ph2={0..3}
__device__ __forceinline__ int jmap(int ph, int e, int tid) {
    switch (ph) {
        case 0:  return (e << 8) | tid;
        case 1:  return (tid & 15) | (e << 4) | ((tid >> 4) << 8);
        default: return e | (tid << 4);
    }
}

__global__ void __launch_bounds__(TPB, 2) pass_kernel(PassDesc pd,
    const u64* __restrict__ src, u64* __restrict__ dst,
    const float* __restrict__ x, const float* __restrict__ w)
{
    __shared__ u64 tile[TPAD];
    __shared__ u64 gmx[TB][8];
    __shared__ float sc[NQ], ss[NQ];
    __shared__ float wred[TPB / 32][NQ];

    const int tid = threadIdx.x;
    const int idx = pd.rev ? ((int)gridDim.x - 1 - (int)blockIdx.x) : (int)blockIdx.x;
    const int b = idx >> 4;
    const int tsel = idx & 15;

    // One thread per Rot builds packed f32x2 gate constants:
    // Rot(phi,theta,omega) = RZ(omega) RY(theta) RZ(phi)
    if (tid < TB) {
        int q = pd.rotq[tid];
        if (q >= 0) {
            const float* wp = w + (pd.layer * NQ + q) * 3;
            float phi = wp[0], th = wp[1], om = wp[2];
            float stt, ct, sa, ca, sb, cb;
            sincosf(0.5f * th, &stt, &ct);
            sincosf(0.5f * (phi + om), &sa, &ca);
            sincosf(0.5f * (phi - om), &sb, &cb);
            float u00r =  ct * ca, u00i = -ct * sa;
            float u01r = -stt * cb, u01i = -stt * sb;
            float u10r =  stt * cb, u10i = -stt * sb;
            float u11r =  ct * ca, u11i =  ct * sa;
            gmx[tid][0] = pack2(u00r, u00r); gmx[tid][1] = pack2(-u00i, u00i);
            gmx[tid][2] = pack2(u01r, u01r); gmx[tid][3] = pack2(-u01i, u01i);
            gmx[tid][4] = pack2(u10r, u10r); gmx[tid][5] = pack2(-u10i, u10i);
            gmx[tid][6] = pack2(u11r, u11r); gmx[tid][7] = pack2(-u11i, u11i);
        }
    }
    if (pd.synth && tid < NQ)
        sincosf(0.5f * x[b * NQ + tid], &ss[tid], &sc[tid]);

    const u64* sg = src + ((size_t)b << NQ);
    u64* dg = dst + ((size_t)b << NQ);
    u64 v[EPT];

    if (!pd.synth) {
        // Linear read: the previous pass wrote the state in THIS pass's layout.
        const u32 rbase = (u32)tsel << TB;
#pragma unroll
        for (int e = 0; e < EPT; e++)
            v[e] = __ldcg(sg + (rbase | (e << 8) | tid));
    }
    __syncthreads();
    if (pd.synth) {
        // amp(g) = (-i)^popc(g) * prod_q (bit_q ? sin(x_q/2) : cos(x_q/2))
        u32 gbase = 0;
#pragma unroll
        for (int i = 0; i < NFIX; i++)
            gbase |= ((u32)(tsel >> i) & 1u) << pd.fpos[i];
#pragma unroll
        for (int lb = 0; lb < 8; lb++)
            gbase |= ((u32)(tid >> lb) & 1u) << pd.fb[lb];
        u32 fp[4];
#pragma unroll
        for (int k = 0; k < 4; k++) fp[k] = 1u << pd.fb[8 + k];
#pragma unroll
        for (int e = 0; e < EPT; e++) {
            u32 g = gbase;
#pragma unroll
            for (int k = 0; k < 4; k++) if ((e >> k) & 1) g |= fp[k];
            float mag = 1.0f;
#pragma unroll
            for (int q = 0; q < NQ; q++)
                mag *= ((g >> q) & 1u) ? ss[q] : sc[q];
            int k4 = __popc(g) & 3;
            float re = (k4 == 0) ? mag : ((k4 == 2) ? -mag : 0.0f);
            float im = (k4 == 1) ? -mag : ((k4 == 3) ? mag : 0.0f);
            v[e] = pack2(re, im);
        }
    }

    const int nph = pd.nphases;
    for (int ph = 0; ph < nph; ph++) {
        if (ph > 0) {
            // No pre-barrier needed: within a phase each thread's read set
            // equals its own write set (jmap is a per-thread bijection); the
            // post-store barrier of the previous phase orders cross-thread.
#pragma unroll
            for (int e = 0; e < EPT; e++) {
                int j = jmap(ph, e, tid);
                v[e] = tile[SKEW(j)];
            }
        }
        const int lb0 = 8 - 4 * ph;
#pragma unroll
        for (int s = 0; s < 4; s++) {
            int lb = lb0 + s;
            if (pd.rotq[lb] >= 0) {
                u64 c00r = gmx[lb][0], c00i = gmx[lb][1], c01r = gmx[lb][2], c01i = gmx[lb][3];
                u64 c10r = gmx[lb][4], c10i = gmx[lb][5], c11r = gmx[lb][6], c11i = gmx[lb][7];
#pragma unroll
                for (int p = 0; p < EPT / 2; p++) {
                    int elo = ((p >> s) << (s + 1)) | (p & ((1 << s) - 1));
                    int ehi = elo | (1 << s);
                    u64 a = v[elo], bb = v[ehi];
                    u64 sa_ = swap64(a), sb_ = swap64(bb);
                    v[elo] = f2fma(c00r, a, f2fma(c00i, sa_, f2fma(c01r, bb, f2mul(c01i, sb_))));
                    v[ehi] = f2fma(c10r, a, f2fma(c10i, sa_, f2fma(c11r, bb, f2mul(c11i, sb_))));
                }
            }
        }
#pragma unroll
        for (int e = 0; e < EPT; e++) {
            int j = jmap(ph, e, tid);
            tile[SKEW(j)] = v[e];
        }
        __syncthreads();
    }

    // gather: f[j] = s[G(j)], G = composed CNOT chain (XOR-linear, local space)
    u32 srcbase = 0;
#pragma unroll
    for (int lb = 0; lb < 8; lb++)
        if ((tid >> lb) & 1) srcbase ^= pd.grow[lb];
    u32 gp[4];
#pragma unroll
    for (int k = 0; k < 4; k++) gp[k] = pd.grow[8 + k];

    if (!pd.measure) {
        // write into NEXT pass's layout in the OTHER buffer (race-free ping-pong)
        u32 wbase = 0;
#pragma unroll
        for (int i = 0; i < NFIX; i++)
            wbase |= ((u32)(tsel >> i) & 1u) << pd.outfixpos[i];
#pragma unroll
        for (int lb = 0; lb < 8; lb++)
            wbase |= ((u32)(tid >> lb) & 1u) << pd.outpos[lb];
        u32 w4[4];
#pragma unroll
        for (int k = 0; k < 4; k++) w4[k] = 1u << pd.outpos[8 + k];
#pragma unroll
        for (int e = 0; e < EPT; e++) {
            u32 s2 = srcbase;
            u32 wa = wbase;
#pragma unroll
            for (int k = 0; k < 4; k++) {
                if ((e >> k) & 1) { s2 ^= gp[k]; wa |= w4[k]; }
            }
            dg[wa] = tile[SKEW(s2)];
        }
    } else {
        u32 gbase = 0;
#pragma unroll
        for (int i = 0; i < NFIX; i++)
            gbase |= ((u32)(tsel >> i) & 1u) << pd.fpos[i];
#pragma unroll
        for (int lb = 0; lb < 8; lb++)
            gbase |= ((u32)(tid >> lb) & 1u) << pd.fb[lb];
        float p16[EPT];
#pragma unroll
        for (int e = 0; e < EPT; e++) {
            u32 s2 = srcbase;
#pragma unroll
            for (int k = 0; k < 4; k++) if ((e >> k) & 1) s2 ^= gp[k];
            u64 val = tile[SKEW(s2)];
            float2 c = *(float2*)&val;
            p16[e] = c.x * c.x + c.y * c.y;
        }
        float s_ = 0.0f, z[4] = {0.0f, 0.0f, 0.0f, 0.0f};
#pragma unroll
        for (int e = 0; e < EPT; e++) {
            s_ += p16[e];
#pragma unroll
            for (int k = 0; k < 4; k++)
                z[k] += ((e >> k) & 1) ? -p16[e] : p16[e];
        }
        float acc[NQ];
#pragma unroll
        for (int q = 0; q < NQ; q++) {
            float t = ((gbase >> q) & 1u) ? -s_ : s_;
#pragma unroll
            for (int k = 0; k < 4; k++)
                if (q == pd.fb[8 + k]) t = z[k];   // gbase bit is 0 there
            acc[q] = t;
        }
#pragma unroll
        for (int q = 0; q < NQ; q++)
#pragma unroll
            for (int o = 16; o > 0; o >>= 1)
                acc[q] += __shfl_xor_sync(0xffffffffu, acc[q], o);
        if ((tid & 31) == 0) {
#pragma unroll
            for (int q = 0; q < NQ; q++)
                wred[tid >> 5][q] = acc[q];
        }
        __syncthreads();
        if (tid < NQ) {
            float sm = 0.0f;
#pragma unroll
            for (int wg = 0; wg < TPB / 32; wg++)
                sm += wred[wg][tid];
            g_part[((b << 4) | tsel) * NQ + tid] = sm;
        }
    }
}

__global__ void finalize_kernel(float* __restrict__ out)
{
    int i = blockIdx.x * blockDim.x + threadIdx.x;
    if (i < NB * NQ) {
        int b = i / NQ, q = i % NQ;
        float s = 0.0f;
#pragma unroll
        for (int t = 0; t < NT; t++)
            s += g_part[(b * NT + t) * NQ + q];
        out[i] = s;
    }
}

// ---------------------------------------------------------------------------
// Host scheduling: exact gate schedule proven in R4/R6/R8/R13 (pass A =
// Rot 0..11 + in-tile ring CNOTs; pass B = Rot 12..15 + deferred CNOTs;
// deferral commutes for all r<=6). State between passes is stored
// bit-permuted (next pass's free bits at addr bits 0..11) in PING-PONG
// buffers. This round: EPT=16 / TPB=256 -> pass A 3 phases, pass B 1 phase
// (pass-B rots always land at local bits 8..11 since rots are placed last
// and pass B has exactly 4 of them).
// ---------------------------------------------------------------------------
static void compose_cnots(u32* grow, const u32* cm, const u32* tm, int ncn)
{
    for (int lb = 0; lb < TB; lb++) {
        u32 s = 1u << lb;
        for (int i = ncn - 1; i >= 0; i--)
            if (s & cm[i]) s ^= tm[i];
        grow[lb] = s;
    }
}

static void order_tile(const bool* inSet, const int* prevLanes,
                       const bool* prefSet, const bool* rotSet, int* fb)
{
    bool used[NQ] = {};
    int n = 0;
    if (prevLanes) {
        for (int i = 0; i < 5; i++) {
            int q = prevLanes[i];
            if (q >= 0 && inSet[q] && !used[q]) { fb[n++] = q; used[q] = true; }
        }
    }
    while (n < 5) {
        int pick = -1;
        for (int tier = 0; tier < 4 && pick < 0; tier++)
            for (int q = 0; q < NQ && pick < 0; q++)
                if (inSet[q] && !used[q]) {
                    bool ok;
                    switch (tier) {
                        case 0: ok = prefSet && prefSet[q] && !rotSet[q]; break;
                        case 1: ok = !rotSet[q]; break;
                        case 2: ok = prefSet && prefSet[q]; break;
                        default: ok = true; break;
                    }
                    if (ok) pick = q;
                }
        fb[n++] = pick; used[pick] = true;
    }
    for (int q = 0; q < NQ; q++)            // middle: remaining non-rot
        if (inSet[q] && !used[q] && !rotSet[q]) { fb[n++] = q; used[q] = true; }
    for (int q = 0; q < NQ; q++)            // rot qubits last (high local bits)
        if (inSet[q] && !used[q]) { fb[n++] = q; used[q] = true; }
}

static void build_passes(PassDesc* pds)
{
    static bool tiles[NPASS][NQ], rots[NPASS][NQ];
    static int cms[NPASS][NQ], tms[NPASS][NQ], ncns[NPASS];
    static int fbs[NPASS][TB], fposs[NPASS][NFIX];

    for (int l = 0; l < NL; l++) {
        int r = (l % (NQ - 1)) + 1;
        bool inA[NQ];
        for (int q = 0; q < NQ; q++)
            inA[q] = (q <= 11 && (q + r) % NQ <= 11);

        int mA = 2 * l, mB = 2 * l + 1;
        for (int q = 0; q < NQ; q++) {
            tiles[mA][q] = (q < TB);
            rots[mA][q] = (q < TB);
        }
        ncns[mA] = 0;
        for (int q = 0; q < NQ; q++)
            if (inA[q]) { cms[mA][ncns[mA]] = q; tms[mA][ncns[mA]] = (q + r) % NQ; ncns[mA]++; }

        bool touched[NQ] = {};
        for (int q = TB; q < NQ; q++) touched[q] = true;
        for (int q = 0; q < NQ; q++)
            if (!inA[q]) { touched[q] = true; touched[(q + r) % NQ] = true; }
        int cnt = 0;
        for (int q = 0; q < NQ; q++) if (touched[q]) cnt++;
        for (int q = 0; q < NQ && cnt < TB; q++)
            if (!touched[q]) { touched[q] = true; cnt++; }
        for (int q = 0; q < NQ; q++) {
            tiles[mB][q] = touched[q];
            rots[mB][q] = (q >= TB);
        }
        ncns[mB] = 0;
        for (int q = 0; q < NQ; q++)
            if (!inA[q]) { cms[mB][ncns[mB]] = q; tms[mB][ncns[mB]] = (q + r) % NQ; ncns[mB]++; }
    }

    int prevLanes[5] = {-1, -1, -1, -1, -1};
    for (int m = 0; m < NPASS; m++) {
        bool pref[NQ]; bool hasPref = false;
        for (int q = 0; q < NQ; q++) pref[q] = false;
        if (m + 1 < NPASS) {
            for (int q = 0; q < NQ; q++) {
                bool p = tiles[m + 1][q];
                if (m + 2 < NPASS) p = p && tiles[m + 2][q];
                pref[q] = p;
            }
            hasPref = true;
        }
        order_tile(tiles[m], (m > 0) ? prevLanes : (const int*)0,
                   hasPref ? pref : (const bool*)0, rots[m], fbs[m]);
        for (int i = 0; i < 5; i++) prevLanes[i] = fbs[m][i];
        int xi = 0;
        for (int q = 0; q < NQ; q++)
            if (!tiles[m][q]) fposs[m][xi++] = q;
    }

    for (int m = 0; m < NPASS; m++) {
        PassDesc& pd = pds[m];
        memset(&pd, 0, sizeof(pd));
        pd.layer = m / 2;
        pd.synth = (m == 0);
        pd.measure = (m == NPASS - 1);
        pd.rev = (m & 1);
        int lq[NQ];
        for (int q = 0; q < NQ; q++) lq[q] = -1;
        for (int i = 0; i < TB; i++) { pd.fb[i] = fbs[m][i]; lq[fbs[m][i]] = i; }
        for (int i = 0; i < NFIX; i++) pd.fpos[i] = fposs[m][i];
        int minRot = TB;
        for (int i = 0; i < TB; i++) {
            pd.rotq[i] = rots[m][pd.fb[i]] ? pd.fb[i] : -1;
            if (pd.rotq[i] >= 0 && i < minRot) minRot = i;
        }
        pd.nphases = (TB - minRot + 3) / 4;   // A: 3, B: 1
        u32 cm[NQ], tm[NQ];
        for (int i = 0; i < ncns[m]; i++) {
            cm[i] = 1u << lq[cms[m][i]];
            tm[i] = 1u << lq[tms[m][i]];
        }
        compose_cnots(pd.grow, cm, tm, ncns[m]);
        if (m + 1 < NPASS) {
            int pos[NQ];
            for (int i = 0; i < TB; i++)   pos[fbs[m + 1][i]] = i;
            for (int i = 0; i < NFIX; i++) pos[fposs[m + 1][i]] = TB + i;
            for (int i = 0; i < TB; i++)   pd.outpos[i] = pos[pd.fb[i]];
            for (int i = 0; i < NFIX; i++) pd.outfixpos[i] = pos[pd.fpos[i]];
        }
    }
}

extern "C" void kernel_launch(void* const* d_in, const int* in_sizes, int n_in,
                              void* d_out, int out_size)
{
    const float* x = (const float*)d_in[0];   // (512, 16)
    const float* w = (const float*)d_in[1];   // (6, 16, 3)
    float* out = (float*)d_out;               // (512, 16) float32

    PassDesc pds[NPASS];
    build_passes(pds);

    u64* bufs[2];
    cudaGetSymbolAddress((void**)&bufs[0], g_buf0);
    cudaGetSymbolAddress((void**)&bufs[1], g_buf1);

    dim3 grid(NB * NT);
    for (int p = 0; p < NPASS; p++) {
        const u64* src = bufs[p & 1];
        u64* dst = bufs[(p + 1) & 1];
        pass_kernel<<<grid, TPB>>>(pds[p], src, dst, x, w);
    }

    finalize_kernel<<<(NB * NQ + 255) / 256, 256>>>(out);
}